// round 3
// baseline (speedup 1.0000x reference)
#include <cuda_runtime.h>
#include <math.h>

// Problem constants (fixed by the dataset)
#define DDIM  2048
#define NEXP  64
#define NOUT  128     // 64 gate logits + 64 noise logits
#define TOPK  8
#define MTOK  16384   // B*S

// GEMM tiling: 256 threads, thread tile 8 rows x 4 cols, rows paired for f32x2
#define BM 128
#define BN 64
#define BK 32
#define NTHREADS 256

// Scratch for logits (gate | noise), [MTOK][NOUT]. Static device array (no allocs).
__device__ float g_logits[MTOK * NOUT];

// ---- f32x2 packed helpers (inline PTX; ptxas won't auto-fuse) -------------
__device__ __forceinline__ unsigned long long dup2(float x) {
    unsigned long long d; unsigned int u = __float_as_uint(x);
    asm("mov.b64 %0, {%1, %1};" : "=l"(d) : "r"(u));
    return d;
}
__device__ __forceinline__ void ffma2(unsigned long long& d,
                                      unsigned long long a, unsigned long long b) {
    asm("fma.rn.f32x2 %0, %1, %2, %0;" : "+l"(d) : "l"(a), "l"(b));
}
__device__ __forceinline__ unsigned long long fmul2(unsigned long long a,
                                                    unsigned long long b) {
    unsigned long long d;
    asm("mul.rn.f32x2 %0, %1, %2;" : "=l"(d) : "l"(a), "l"(b));
    return d;
}
__device__ __forceinline__ void unpack2(unsigned long long v, float& lo, float& hi) {
    unsigned int a, b;
    asm("mov.b64 {%0, %1}, %2;" : "=r"(a), "=r"(b) : "l"(v));
    lo = __uint_as_float(a); hi = __uint_as_float(b);
}

// ---------------------------------------------------------------------------
// Kernel 1: dual GEMM, accuracy-hardened.
//   fp32 f32x2 FMA chains of length BK=32, folded into fp64 masters each chunk.
//   Final logit error ~7e-8 abs (vs ~6.5e-7 for a serial 2048 chain).
// blockIdx.y = 0 -> gate half (Wg, cols 0..63); 1 -> noise half (Wn, cols 64..127)
// ---------------------------------------------------------------------------
__global__ __launch_bounds__(NTHREADS, 1) void router_gemm(
    const float* __restrict__ A,    // [M][DDIM]
    const float* __restrict__ Wg,   // [64][DDIM]
    const float* __restrict__ Wn,   // [64][DDIM]
    float* __restrict__ C,          // [M][NOUT]
    int M)
{
    __shared__ __align__(16) float As[BK][BM];   // 16 KB
    __shared__ __align__(16) float Bs[BK][BN];   // 8 KB

    const int tid = threadIdx.x;
    const int tx = tid & 15;          // col group (4 cols each)
    const int ty = tid >> 4;          // row group (8 rows each)
    const int m0 = blockIdx.x * BM;
    const int nhalf = blockIdx.y;
    const float* W = nhalf ? Wn : Wg;

    // A loader: each thread loads 16 floats (half a k-row) of one m-row
    const int ar  = tid >> 1;            // 0..127
    const int akb = (tid & 1) * 16;      // 0 or 16
    // B loader: each thread loads 8 floats of one n-row
    const int br  = tid >> 2;            // 0..63
    const int bkb = (tid & 3) * 8;       // 0,8,16,24

    double mast[32];                      // fp64 master accumulators, [8 rows][4 cols]
#pragma unroll
    for (int i = 0; i < 32; i++) mast[i] = 0.0;

    const float* Arow = A + (size_t)(m0 + ar) * DDIM + akb;
    const float* Wrow = W + (size_t)br * DDIM + bkb;

    for (int k0 = 0; k0 < DDIM; k0 += BK) {
        // ---- stage tiles (transposed: [k][m] / [k][n])
#pragma unroll
        for (int q = 0; q < 4; q++) {
            float4 v = *(const float4*)(Arow + k0 + 4 * q);
            As[akb + 4 * q + 0][ar] = v.x;
            As[akb + 4 * q + 1][ar] = v.y;
            As[akb + 4 * q + 2][ar] = v.z;
            As[akb + 4 * q + 3][ar] = v.w;
        }
#pragma unroll
        for (int q = 0; q < 2; q++) {
            float4 v = *(const float4*)(Wrow + k0 + 4 * q);
            Bs[bkb + 4 * q + 0][br] = v.x;
            Bs[bkb + 4 * q + 1][br] = v.y;
            Bs[bkb + 4 * q + 2][br] = v.z;
            Bs[bkb + 4 * q + 3][br] = v.w;
        }
        __syncthreads();

        // ---- fp32 chunk accumulators (4 row-pairs x 4 cols), f32x2 packed
        unsigned long long c2[16];
#pragma unroll
        for (int kk = 0; kk < BK; kk++) {
            // row pairs come straight from 16B shared loads (no packing movs)
            const ulonglong2* ap = (const ulonglong2*)&As[kk][ty * 8];
            ulonglong2 aA = ap[0];
            ulonglong2 aB = ap[1];
            unsigned long long apair[4] = { aA.x, aA.y, aB.x, aB.y };
            float4 bf = *(const float4*)&Bs[kk][tx * 4];
            unsigned long long b[4] = { dup2(bf.x), dup2(bf.y), dup2(bf.z), dup2(bf.w) };
            if (kk == 0) {
#pragma unroll
                for (int p = 0; p < 4; p++)
#pragma unroll
                    for (int j = 0; j < 4; j++)
                        c2[p * 4 + j] = fmul2(apair[p], b[j]);
            } else {
#pragma unroll
                for (int p = 0; p < 4; p++)
#pragma unroll
                    for (int j = 0; j < 4; j++)
                        ffma2(c2[p * 4 + j], apair[p], b[j]);
            }
        }
        __syncthreads();

        // ---- fold chunk into fp64 masters (fp64 pipe, overlaps fma pipe)
#pragma unroll
        for (int p = 0; p < 4; p++)
#pragma unroll
            for (int j = 0; j < 4; j++) {
                float lo, hi;
                unpack2(c2[p * 4 + j], lo, hi);
                mast[(2 * p + 0) * 4 + j] += (double)lo;
                mast[(2 * p + 1) * 4 + j] += (double)hi;
            }
    }

    // ---- write logits (round once at the end)
#pragma unroll
    for (int i = 0; i < 8; i++) {
        float4 v;
        v.x = (float)mast[i * 4 + 0];
        v.y = (float)mast[i * 4 + 1];
        v.z = (float)mast[i * 4 + 2];
        v.w = (float)mast[i * 4 + 3];
        *(float4*)(C + (size_t)(m0 + ty * 8 + i) * NOUT + nhalf * 64 + tx * 4) = v;
    }
}

// jax.nn.softplus(x) = max(x,0) + log1p(exp(-|x|)), evaluated in fp64
__device__ __forceinline__ double softplus_d(double x) {
    return fmax(x, 0.0) + log1p(exp(-fabs(x)));
}

// ---------------------------------------------------------------------------
// Kernel 2: per-token epilogue. 1 warp per token, 2 experts per lane.
//   l = gate + noise * softplus(noise_logit)   [fp64 combine]
//   ordering (top-8) decided on fp64 l; gates/vals written in fp32.
// Output layout: [vals M*8][inds M*8 (value-cast)][gates M*64]
// ---------------------------------------------------------------------------
__global__ __launch_bounds__(256) void router_epilogue(
    const float* __restrict__ logits,   // [M][NOUT]
    const float* __restrict__ noise,    // [M][64]
    float* __restrict__ out,
    int M)
{
    int warp = (blockIdx.x * blockDim.x + threadIdx.x) >> 5;
    int lane = threadIdx.x & 31;
    if (warp >= M) return;

    const float* L  = logits + (size_t)warp * NOUT;
    const float* NZ = noise  + (size_t)warp * NEXP;

    const int e0 = lane, e1 = lane + 32;

    double gl0 = (double)L[e0],      gl1 = (double)L[e1];
    double nl0 = (double)L[64 + e0], nl1 = (double)L[64 + e1];
    double nz0 = (double)NZ[e0],     nz1 = (double)NZ[e1];

    double l0 = gl0 + nz0 * softplus_d(nl0);
    double l1 = gl1 + nz1 * softplus_d(nl1);

    // softmax over 64 in fp32 (values only; ordering uses fp64 l)
    float f0 = (float)l0, f1 = (float)l1;
    float mx = fmaxf(f0, f1);
#pragma unroll
    for (int off = 16; off > 0; off >>= 1)
        mx = fmaxf(mx, __shfl_xor_sync(0xffffffffu, mx, off));
    float ex0 = expf(f0 - mx), ex1 = expf(f1 - mx);
    float s = ex0 + ex1;
#pragma unroll
    for (int off = 16; off > 0; off >>= 1)
        s += __shfl_xor_sync(0xffffffffu, s, off);
    float inv = 1.0f / s;
    float g0 = ex0 * inv, g1 = ex1 * inv;

    // gates output
    float* gates_out = out + (size_t)M * (2 * TOPK) + (size_t)warp * NEXP;
    gates_out[e0] = g0;
    gates_out[e1] = g1;

    // top-8 by repeated argmax on fp64 l (lower index wins ties, like lax.top_k)
    double c0 = l0, c1 = l1;
    float* vals_out = out + (size_t)warp * TOPK;
    float* inds_out = out + (size_t)M * TOPK + (size_t)warp * TOPK;

#pragma unroll
    for (int t = 0; t < TOPK; t++) {
        double bv; int bi;
        if (c0 >= c1) { bv = c0; bi = e0; } else { bv = c1; bi = e1; }
#pragma unroll
        for (int off = 16; off > 0; off >>= 1) {
            double ov = __shfl_xor_sync(0xffffffffu, bv, off);
            int    oi = __shfl_xor_sync(0xffffffffu, bi, off);
            if (ov > bv || (ov == bv && oi < bi)) { bv = ov; bi = oi; }
        }
        // fetch the gate value owned by the winning lane
        float gw0 = __shfl_sync(0xffffffffu, g0, bi & 31);
        float gw1 = __shfl_sync(0xffffffffu, g1, bi & 31);
        if (lane == 0) {
            vals_out[t] = (bi < 32) ? gw0 : gw1;
            inds_out[t] = (float)bi;
        }
        if (bi == e0) c0 = -1e30;
        else if (bi == e1) c1 = -1e30;
    }
}

extern "C" void kernel_launch(void* const* d_in, const int* in_sizes, int n_in,
                              void* d_out, int out_size) {
    const float* hidden = (const float*)d_in[0];   // [B,S,D]
    const float* Wg     = (const float*)d_in[1];   // [64,D]
    const float* Wn     = (const float*)d_in[2];   // [64,D]
    const float* noise  = (const float*)d_in[3];   // [B,S,64]
    float* out = (float*)d_out;

    int M = in_sizes[0] / DDIM;                    // 16384

    float* logits;
    cudaGetSymbolAddress((void**)&logits, g_logits);

    dim3 grid(M / BM, 2);
    router_gemm<<<grid, NTHREADS>>>(hidden, Wg, Wn, logits, M);

    int blocks = (M * 32 + 255) / 256;
    router_epilogue<<<blocks, 256>>>(logits, noise, out, M);
}

// round 5
// speedup vs baseline: 3.9649x; 3.9649x over previous
#include <cuda_runtime.h>
#include <math.h>

// Problem constants (fixed by the dataset)
#define DDIM  2048
#define NEXP  64
#define NOUT  128     // 64 gate logits + 64 noise logits
#define TOPK  8
#define MTOK  16384   // B*S

// GEMM tiling: 256 threads, thread tile 8 rows x 4 cols, rows paired for f32x2
#define BM 128
#define BN 64
#define BK 32
#define NTHREADS 256

// Gap threshold (logit units) below which we redo ordering in fp64.
#define GAP_THETA 1e-4f

// Scratch for logits (gate | noise), [MTOK][NOUT]. Static device array (no allocs).
__device__ float g_logits[MTOK * NOUT];

// ---- f32x2 packed helpers (inline PTX; ptxas won't auto-fuse) -------------
__device__ __forceinline__ unsigned long long dup2(float x) {
    unsigned long long d; unsigned int u = __float_as_uint(x);
    asm("mov.b64 %0, {%1, %1};" : "=l"(d) : "r"(u));
    return d;
}
__device__ __forceinline__ void ffma2(unsigned long long& d,
                                      unsigned long long a, unsigned long long b) {
    asm("fma.rn.f32x2 %0, %1, %2, %0;" : "+l"(d) : "l"(a), "l"(b));
}
__device__ __forceinline__ unsigned long long fmul2(unsigned long long a,
                                                    unsigned long long b) {
    unsigned long long d;
    asm("mul.rn.f32x2 %0, %1, %2;" : "=l"(d) : "l"(a), "l"(b));
    return d;
}
__device__ __forceinline__ void unpack2(unsigned long long v, float& lo, float& hi) {
    unsigned int a, b;
    asm("mov.b64 {%0, %1}, %2;" : "=r"(a), "=r"(b) : "l"(v));
    lo = __uint_as_float(a); hi = __uint_as_float(b);
}

// ---------------------------------------------------------------------------
// Kernel 1: dual GEMM.
//   fp32 f32x2 FMA chains of length BK=32, folded into scalar fp32 Kahan
//   master accumulators each chunk (error ~2 ulp, chain-length independent).
//   Register-staged prefetch of the next global chunk hides HBM latency.
// blockIdx.y = 0 -> gate half (Wg, cols 0..63); 1 -> noise half (Wn, 64..127)
// ---------------------------------------------------------------------------
__global__ __launch_bounds__(NTHREADS) void router_gemm(
    const float* __restrict__ A,    // [M][DDIM]
    const float* __restrict__ Wg,   // [64][DDIM]
    const float* __restrict__ Wn,   // [64][DDIM]
    float* __restrict__ C,          // [M][NOUT]
    int M)
{
    __shared__ __align__(16) float As[BK][BM];   // 16 KB
    __shared__ __align__(16) float Bs[BK][BN];   // 8 KB

    const int tid = threadIdx.x;
    const int tx = tid & 15;          // col group (4 cols each)
    const int ty = tid >> 4;          // row group (8 rows each)
    const int m0 = blockIdx.x * BM;
    const float* W = blockIdx.y ? Wn : Wg;
    const int nhalf = blockIdx.y;

    // A loader: each thread loads 16 floats (half a k-row) of one m-row
    const int ar  = tid >> 1;            // 0..127
    const int akb = (tid & 1) * 16;      // 0 or 16
    // B loader: each thread loads 8 floats of one n-row
    const int br  = tid >> 2;            // 0..63
    const int bkb = (tid & 3) * 8;       // 0,8,16,24

    // Kahan masters: 32 scalar sums + 32 compensations
    float s[32], comp[32];
#pragma unroll
    for (int i = 0; i < 32; i++) { s[i] = 0.f; comp[i] = 0.f; }

    const float* Arow = A + (size_t)(m0 + ar) * DDIM + akb;
    const float* Wrow = W + (size_t)br * DDIM + bkb;

    // prefetch chunk 0 into registers
    float4 pa[4], pb[2];
#pragma unroll
    for (int q = 0; q < 4; q++) pa[q] = *(const float4*)(Arow + 4 * q);
#pragma unroll
    for (int q = 0; q < 2; q++) pb[q] = *(const float4*)(Wrow + 4 * q);

    for (int k0 = 0; k0 < DDIM; k0 += BK) {
        // ---- stage prefetched tiles (transposed: [k][m] / [k][n])
#pragma unroll
        for (int q = 0; q < 4; q++) {
            As[akb + 4 * q + 0][ar] = pa[q].x;
            As[akb + 4 * q + 1][ar] = pa[q].y;
            As[akb + 4 * q + 2][ar] = pa[q].z;
            As[akb + 4 * q + 3][ar] = pa[q].w;
        }
#pragma unroll
        for (int q = 0; q < 2; q++) {
            Bs[bkb + 4 * q + 0][br] = pb[q].x;
            Bs[bkb + 4 * q + 1][br] = pb[q].y;
            Bs[bkb + 4 * q + 2][br] = pb[q].z;
            Bs[bkb + 4 * q + 3][br] = pb[q].w;
        }
        __syncthreads();

        // ---- prefetch next chunk (global -> regs) while computing this one
        if (k0 + BK < DDIM) {
#pragma unroll
            for (int q = 0; q < 4; q++) pa[q] = *(const float4*)(Arow + k0 + BK + 4 * q);
#pragma unroll
            for (int q = 0; q < 2; q++) pb[q] = *(const float4*)(Wrow + k0 + BK + 4 * q);
        }

        // ---- fp32 chunk accumulators (4 row-pairs x 4 cols), f32x2 packed
        unsigned long long c2[16];
#pragma unroll
        for (int kk = 0; kk < BK; kk++) {
            const ulonglong2* ap = (const ulonglong2*)&As[kk][ty * 8];
            ulonglong2 aA = ap[0];
            ulonglong2 aB = ap[1];
            unsigned long long apair[4] = { aA.x, aA.y, aB.x, aB.y };
            float4 bf = *(const float4*)&Bs[kk][tx * 4];
            unsigned long long b[4] = { dup2(bf.x), dup2(bf.y), dup2(bf.z), dup2(bf.w) };
            if (kk == 0) {
#pragma unroll
                for (int p = 0; p < 4; p++)
#pragma unroll
                    for (int j = 0; j < 4; j++)
                        c2[p * 4 + j] = fmul2(apair[p], b[j]);
            } else {
#pragma unroll
                for (int p = 0; p < 4; p++)
#pragma unroll
                    for (int j = 0; j < 4; j++)
                        ffma2(c2[p * 4 + j], apair[p], b[j]);
            }
        }
        __syncthreads();

        // ---- Kahan fold of the chunk into fp32 masters (no fp64 anywhere)
#pragma unroll
        for (int p = 0; p < 4; p++)
#pragma unroll
            for (int j = 0; j < 4; j++) {
                float lo, hi;
                unpack2(c2[p * 4 + j], lo, hi);   // free (register aliasing)
                {
                    int idx = (2 * p + 0) * 4 + j;
                    float y = lo - comp[idx];
                    float t = s[idx] + y;
                    comp[idx] = (t - s[idx]) - y;
                    s[idx] = t;
                }
                {
                    int idx = (2 * p + 1) * 4 + j;
                    float y = hi - comp[idx];
                    float t = s[idx] + y;
                    comp[idx] = (t - s[idx]) - y;
                    s[idx] = t;
                }
            }
    }

    // ---- write logits
#pragma unroll
    for (int i = 0; i < 8; i++) {
        float4 v;
        v.x = s[i * 4 + 0];
        v.y = s[i * 4 + 1];
        v.z = s[i * 4 + 2];
        v.w = s[i * 4 + 3];
        *(float4*)(C + (size_t)(m0 + ty * 8 + i) * NOUT + nhalf * 64 + tx * 4) = v;
    }
}

// jax.nn.softplus(x) = max(x,0) + log1p(exp(-|x|))
__device__ __forceinline__ float softplus_f(float x) {
    return fmaxf(x, 0.f) + log1pf(expf(-fabsf(x)));
}
__device__ __forceinline__ double softplus_d(double x) {
    return fmax(x, 0.0) + log1p(exp(-fabs(x)));
}

// ---------------------------------------------------------------------------
// Kernel 2: per-token epilogue. 1 warp per token, 2 experts per lane.
//   Fast path: fp32 combine + softmax + top-9 argmax scan with gap check.
//   If any adjacent gap among the top-9 logits < GAP_THETA, the whole warp
//   redoes the ordering in fp64 (rare: near-tie tokens only).
// Output layout: [vals M*8][inds M*8 (value-cast)][gates M*64]
// ---------------------------------------------------------------------------
__global__ __launch_bounds__(256) void router_epilogue(
    const float* __restrict__ logits,   // [M][NOUT]
    const float* __restrict__ noise,    // [M][64]
    float* __restrict__ out,
    int M)
{
    int warp = (blockIdx.x * blockDim.x + threadIdx.x) >> 5;
    int lane = threadIdx.x & 31;
    if (warp >= M) return;

    const float* L  = logits + (size_t)warp * NOUT;
    const float* NZ = noise  + (size_t)warp * NEXP;

    const int e0 = lane, e1 = lane + 32;

    float gl0 = L[e0],      gl1 = L[e1];
    float nl0 = L[64 + e0], nl1 = L[64 + e1];
    float nz0 = NZ[e0],     nz1 = NZ[e1];

    float l0 = fmaf(nz0, softplus_f(nl0), gl0);
    float l1 = fmaf(nz1, softplus_f(nl1), gl1);

    // softmax over 64 in fp32 (values)
    float mx = fmaxf(l0, l1);
#pragma unroll
    for (int off = 16; off > 0; off >>= 1)
        mx = fmaxf(mx, __shfl_xor_sync(0xffffffffu, mx, off));
    float ex0 = expf(l0 - mx), ex1 = expf(l1 - mx);
    float ssum = ex0 + ex1;
#pragma unroll
    for (int off = 16; off > 0; off >>= 1)
        ssum += __shfl_xor_sync(0xffffffffu, ssum, off);
    float inv = 1.0f / ssum;
    float g0 = ex0 * inv, g1 = ex1 * inv;

    // gates output
    float* gates_out = out + (size_t)M * (2 * TOPK) + (size_t)warp * NEXP;
    gates_out[e0] = g0;
    gates_out[e1] = g1;

    float* vals_out = out + (size_t)warp * TOPK;
    float* inds_out = out + (size_t)M * TOPK + (size_t)warp * TOPK;

    // ---- fast path: top-9 scan on fp32 logits, tracking min adjacent gap
    float c0 = l0, c1 = l1;
    int   top_i[TOPK];
    float top_v[TOPK];            // gate values of winners (uniform in warp)
    float prev = 0.f;
    float mingap = 1e30f;

#pragma unroll
    for (int t = 0; t < TOPK + 1; t++) {
        float bv; int bi;
        if (c0 >= c1) { bv = c0; bi = e0; } else { bv = c1; bi = e1; }
#pragma unroll
        for (int off = 16; off > 0; off >>= 1) {
            float ov = __shfl_xor_sync(0xffffffffu, bv, off);
            int   oi = __shfl_xor_sync(0xffffffffu, bi, off);
            if (ov > bv || (ov == bv && oi < bi)) { bv = ov; bi = oi; }
        }
        if (t > 0) mingap = fminf(mingap, prev - bv);
        prev = bv;
        if (t < TOPK) {
            float gw0 = __shfl_sync(0xffffffffu, g0, bi & 31);
            float gw1 = __shfl_sync(0xffffffffu, g1, bi & 31);
            top_i[t] = bi;
            top_v[t] = (bi < 32) ? gw0 : gw1;
        }
        if (bi == e0) c0 = -1e30f;
        else if (bi == e1) c1 = -1e30f;
    }

    if (mingap > GAP_THETA) {
        // certified ordering: fp32 error (~6e-7) << gap
        if (lane < TOPK) {
            vals_out[lane] = top_v[lane];
            inds_out[lane] = (float)top_i[lane];
        }
        return;
    }

    // ---- slow path (rare near-tie token): redo ordering in fp64
    {
        double d0 = (double)gl0 + (double)nz0 * softplus_d((double)nl0);
        double d1 = (double)gl1 + (double)nz1 * softplus_d((double)nl1);

#pragma unroll
        for (int t = 0; t < TOPK; t++) {
            double bv; int bi;
            if (d0 >= d1) { bv = d0; bi = e0; } else { bv = d1; bi = e1; }
#pragma unroll
            for (int off = 16; off > 0; off >>= 1) {
                double ov = __shfl_xor_sync(0xffffffffu, bv, off);
                int    oi = __shfl_xor_sync(0xffffffffu, bi, off);
                if (ov > bv || (ov == bv && oi < bi)) { bv = ov; bi = oi; }
            }
            float gw0 = __shfl_sync(0xffffffffu, g0, bi & 31);
            float gw1 = __shfl_sync(0xffffffffu, g1, bi & 31);
            if (lane == 0) {
                vals_out[t] = (bi < 32) ? gw0 : gw1;
                inds_out[t] = (float)bi;
            }
            if (bi == e0) d0 = -1e30;
            else if (bi == e1) d1 = -1e30;
        }
    }
}

extern "C" void kernel_launch(void* const* d_in, const int* in_sizes, int n_in,
                              void* d_out, int out_size) {
    const float* hidden = (const float*)d_in[0];   // [B,S,D]
    const float* Wg     = (const float*)d_in[1];   // [64,D]
    const float* Wn     = (const float*)d_in[2];   // [64,D]
    const float* noise  = (const float*)d_in[3];   // [B,S,64]
    float* out = (float*)d_out;

    int M = in_sizes[0] / DDIM;                    // 16384

    float* logits;
    cudaGetSymbolAddress((void**)&logits, g_logits);

    dim3 grid(M / BM, 2);
    router_gemm<<<grid, NTHREADS>>>(hidden, Wg, Wn, logits, M);

    int blocks = (M * 32 + 255) / 256;
    router_epilogue<<<blocks, 256>>>(logits, noise, out, M);
}

// round 6
// speedup vs baseline: 4.2364x; 1.0685x over previous
#include <cuda_runtime.h>
#include <math.h>

#define DDIM  2048
#define NEXP  64
#define NOUT  128
#define TOPK  8

#define BM 128
#define BN 128      // 64 gate cols + 64 noise cols
#define BK 32
#define NT 512
#define NCHUNK (DDIM / BK)   // 64

#define GAP_THETA 1e-4f

// ---- f32x2 packed helpers --------------------------------------------------
__device__ __forceinline__ unsigned long long dup2(float x) {
    unsigned long long d; unsigned int u = __float_as_uint(x);
    asm("mov.b64 %0, {%1, %1};" : "=l"(d) : "r"(u));
    return d;
}
__device__ __forceinline__ void ffma2(unsigned long long& d,
                                      unsigned long long a, unsigned long long b) {
    asm("fma.rn.f32x2 %0, %1, %2, %0;" : "+l"(d) : "l"(a), "l"(b));
}
__device__ __forceinline__ unsigned long long fmul2(unsigned long long a,
                                                    unsigned long long b) {
    unsigned long long d;
    asm("mul.rn.f32x2 %0, %1, %2;" : "=l"(d) : "l"(a), "l"(b));
    return d;
}
__device__ __forceinline__ unsigned long long fadd2(unsigned long long a,
                                                    unsigned long long b) {
    unsigned long long d;
    asm("add.rn.f32x2 %0, %1, %2;" : "=l"(d) : "l"(a), "l"(b));
    return d;
}
__device__ __forceinline__ unsigned long long ffma2o(unsigned long long a,
                                                     unsigned long long b,
                                                     unsigned long long c) {
    unsigned long long d;
    asm("fma.rn.f32x2 %0, %1, %2, %3;" : "=l"(d) : "l"(a), "l"(b), "l"(c));
    return d;
}
__device__ __forceinline__ void unpack2(unsigned long long v, float& lo, float& hi) {
    unsigned int a, b;
    asm("mov.b64 {%0, %1}, %2;" : "=r"(a), "=r"(b) : "l"(v));
    lo = __uint_as_float(a); hi = __uint_as_float(b);
}

__device__ __forceinline__ float softplus_f(float x) {
    return fmaxf(x, 0.f) + log1pf(expf(-fabsf(x)));
}
__device__ __forceinline__ double softplus_d(double x) {
    return fmax(x, 0.0) + log1p(exp(-fabs(x)));
}

// ---------------------------------------------------------------------------
// Fused router: dual GEMM (packed f32x2, packed-Kahan masters, swizzled smem,
// double-buffered) + in-block softmax/top-k epilogue.
// Block: 512 threads, 128 tokens x 128 outputs. Grid: M/128 blocks.
// ---------------------------------------------------------------------------
__global__ __launch_bounds__(NT) void router_fused(
    const float* __restrict__ A,     // [M][DDIM]
    const float* __restrict__ Wg,    // [64][DDIM]
    const float* __restrict__ Wn,    // [64][DDIM]
    const float* __restrict__ noise, // [M][64]
    float* __restrict__ out,
    int M)
{
    extern __shared__ float sm[];
    // layout: buf c: As at c*8192, Bs at c*8192+4096 (floats). Total 64KB.
    // After the loop, Ls[128][128] reuses all 64KB.

    const int tid = threadIdx.x;
    const int tx = tid & 31;          // col group (4 cols)
    const int ty = tid >> 5;          // row group (8 rows) == warp id
    const int m0 = blockIdx.x * BM;

    // loaders: 8 floats (2 float4) per thread per tile
    const int ar = tid >> 2;          // 0..127 (A row / B row)
    const int ag = tid & 3;           // k-group: k in [8*ag, 8*ag+8)
    const int asw = ar ^ (8 * ag);    // swizzled col (conflict-free STS)

    const float* Aptr = A + (size_t)(m0 + ar) * DDIM + ag * 8;
    const float* Bptr = ((ar < 64) ? (Wg + (size_t)ar * DDIM)
                                   : (Wn + (size_t)(ar - 64) * DDIM)) + ag * 8;

    const unsigned long long NEG1 =
        ((unsigned long long)0xBF800000u << 32) | 0xBF800000u;   // (-1,-1)

    unsigned long long s2[16], comp[16];
#pragma unroll
    for (int i = 0; i < 16; i++) { s2[i] = 0ull; comp[i] = 0ull; }

    // prefetch chunk 0
    float4 pa0 = *(const float4*)(Aptr + 0);
    float4 pa1 = *(const float4*)(Aptr + 4);
    float4 pb0 = *(const float4*)(Bptr + 0);
    float4 pb1 = *(const float4*)(Bptr + 4);

    for (int c = 0; c < NCHUNK; c++) {
        float* As = sm + (c & 1) * 8192;
        float* Bs = As + 4096;

        // ---- stage chunk c (regs -> smem), swizzled, conflict-free
        {
            float va[8] = { pa0.x, pa0.y, pa0.z, pa0.w, pa1.x, pa1.y, pa1.z, pa1.w };
            float vb[8] = { pb0.x, pb0.y, pb0.z, pb0.w, pb1.x, pb1.y, pb1.z, pb1.w };
#pragma unroll
            for (int q = 0; q < 8; q++) {
                As[(ag * 8 + q) * 128 + asw] = va[q];
                Bs[(ag * 8 + q) * 128 + asw] = vb[q];
            }
        }
        __syncthreads();

        // ---- prefetch chunk c+1 (covered by compute below)
        if (c + 1 < NCHUNK) {
            const float* ap = Aptr + (c + 1) * BK;
            const float* bp = Bptr + (c + 1) * BK;
            pa0 = *(const float4*)(ap + 0);
            pa1 = *(const float4*)(ap + 4);
            pb0 = *(const float4*)(bp + 0);
            pb1 = *(const float4*)(bp + 4);
        }

        // ---- compute chunk: 32 k-steps, 16 packed FFMA2 each
        unsigned long long c2[16];
#pragma unroll
        for (int g4 = 0; g4 < 4; g4++) {
            const float* Arow = As + ((ty ^ g4) * 8);
            const float* Brow = Bs + (((tx >> 1) ^ g4) * 8 + (tx & 1) * 4);
#pragma unroll
            for (int q = 0; q < 8; q++) {
                const int kk = g4 * 8 + q;
                ulonglong2 aA = *(const ulonglong2*)(Arow + kk * 128);
                ulonglong2 aB = *(const ulonglong2*)(Arow + kk * 128 + 4);
                unsigned long long ap4[4] = { aA.x, aA.y, aB.x, aB.y };
                float4 bf = *(const float4*)(Brow + kk * 128);
                unsigned long long b4[4] = { dup2(bf.x), dup2(bf.y), dup2(bf.z), dup2(bf.w) };
                if (g4 == 0 && q == 0) {
#pragma unroll
                    for (int p = 0; p < 4; p++)
#pragma unroll
                        for (int j = 0; j < 4; j++)
                            c2[p * 4 + j] = fmul2(ap4[p], b4[j]);
                } else {
#pragma unroll
                    for (int p = 0; p < 4; p++)
#pragma unroll
                        for (int j = 0; j < 4; j++)
                            ffma2(c2[p * 4 + j], ap4[p], b4[j]);
                }
            }
        }

        // ---- packed Kahan fold into masters
#pragma unroll
        for (int i = 0; i < 16; i++) {
            unsigned long long y  = ffma2o(NEG1, comp[i], c2[i]);   // x - comp
            unsigned long long t  = fadd2(s2[i], y);                // s + y
            unsigned long long df = ffma2o(NEG1, s2[i], t);         // t - s
            comp[i] = ffma2o(NEG1, y, df);                          // (t-s) - y
            s2[i] = t;
        }
    }

    // ---- dump logits to smem (reuse all buffers as Ls[128][128])
    __syncthreads();
    float* Ls = sm;
#pragma unroll
    for (int p = 0; p < 4; p++)
#pragma unroll
        for (int j = 0; j < 4; j++) {
            float lo, hi;
            unpack2(s2[p * 4 + j], lo, hi);
            Ls[(ty * 8 + 2 * p + 0) * 128 + tx * 4 + j] = lo;
            Ls[(ty * 8 + 2 * p + 1) * 128 + tx * 4 + j] = hi;
        }
    __syncthreads();

    // ---- epilogue: each warp handles 8 tokens
    const int lane = tid & 31;
    const int e0 = lane, e1 = lane + 32;

    for (int t8 = 0; t8 < 8; t8++) {
        const int ml = ty * 8 + t8;           // local token
        const int m  = m0 + ml;               // global token
        const float* L = Ls + ml * 128;
        const float* NZ = noise + (size_t)m * NEXP;

        float gl0 = L[e0],      gl1 = L[e1];
        float nl0 = L[64 + e0], nl1 = L[64 + e1];
        float nz0 = NZ[e0],     nz1 = NZ[e1];

        float l0 = fmaf(nz0, softplus_f(nl0), gl0);
        float l1 = fmaf(nz1, softplus_f(nl1), gl1);

        // softmax over 64
        float mx = fmaxf(l0, l1);
#pragma unroll
        for (int off = 16; off > 0; off >>= 1)
            mx = fmaxf(mx, __shfl_xor_sync(0xffffffffu, mx, off));
        float ex0 = expf(l0 - mx), ex1 = expf(l1 - mx);
        float ssum = ex0 + ex1;
#pragma unroll
        for (int off = 16; off > 0; off >>= 1)
            ssum += __shfl_xor_sync(0xffffffffu, ssum, off);
        float inv = 1.0f / ssum;
        float g0 = ex0 * inv, g1 = ex1 * inv;

        float* gates_out = out + (size_t)M * (2 * TOPK) + (size_t)m * NEXP;
        gates_out[e0] = g0;
        gates_out[e1] = g1;

        float* vals_out = out + (size_t)m * TOPK;
        float* inds_out = out + (size_t)M * TOPK + (size_t)m * TOPK;

        // fast top-9 scan with min-adjacent-gap certificate
        float c0 = l0, c1 = l1;
        int   top_i[TOPK];
        float top_v[TOPK];
        float prev = 0.f, mingap = 1e30f;

#pragma unroll
        for (int t = 0; t < TOPK + 1; t++) {
            float bv; int bi;
            if (c0 >= c1) { bv = c0; bi = e0; } else { bv = c1; bi = e1; }
#pragma unroll
            for (int off = 16; off > 0; off >>= 1) {
                float ov = __shfl_xor_sync(0xffffffffu, bv, off);
                int   oi = __shfl_xor_sync(0xffffffffu, bi, off);
                if (ov > bv || (ov == bv && oi < bi)) { bv = ov; bi = oi; }
            }
            if (t > 0) mingap = fminf(mingap, prev - bv);
            prev = bv;
            if (t < TOPK) {
                float gw0 = __shfl_sync(0xffffffffu, g0, bi & 31);
                float gw1 = __shfl_sync(0xffffffffu, g1, bi & 31);
                top_i[t] = bi;
                top_v[t] = (bi < 32) ? gw0 : gw1;
            }
            if (bi == e0) c0 = -1e30f;
            else if (bi == e1) c1 = -1e30f;
        }

        if (mingap > GAP_THETA) {
            if (lane < TOPK) {
                vals_out[lane] = top_v[lane];
                inds_out[lane] = (float)top_i[lane];
            }
            continue;
        }

        // rare near-tie token: redo ordering in fp64
        {
            double d0 = (double)gl0 + (double)nz0 * softplus_d((double)nl0);
            double d1 = (double)gl1 + (double)nz1 * softplus_d((double)nl1);
#pragma unroll
            for (int t = 0; t < TOPK; t++) {
                double bv; int bi;
                if (d0 >= d1) { bv = d0; bi = e0; } else { bv = d1; bi = e1; }
#pragma unroll
                for (int off = 16; off > 0; off >>= 1) {
                    double ov = __shfl_xor_sync(0xffffffffu, bv, off);
                    int    oi = __shfl_xor_sync(0xffffffffu, bi, off);
                    if (ov > bv || (ov == bv && oi < bi)) { bv = ov; bi = oi; }
                }
                float gw0 = __shfl_sync(0xffffffffu, g0, bi & 31);
                float gw1 = __shfl_sync(0xffffffffu, g1, bi & 31);
                if (lane == 0) {
                    vals_out[t] = (bi < 32) ? gw0 : gw1;
                    inds_out[t] = (float)bi;
                }
                if (bi == e0) d0 = -1e30;
                else if (bi == e1) d1 = -1e30;
            }
        }
    }
}

extern "C" void kernel_launch(void* const* d_in, const int* in_sizes, int n_in,
                              void* d_out, int out_size) {
    const float* hidden = (const float*)d_in[0];
    const float* Wg     = (const float*)d_in[1];
    const float* Wn     = (const float*)d_in[2];
    const float* noise  = (const float*)d_in[3];
    float* out = (float*)d_out;

    int M = in_sizes[0] / DDIM;     // 16384

    static int smem_set = 0;
    if (!smem_set) {
        cudaFuncSetAttribute(router_fused,
                             cudaFuncAttributeMaxDynamicSharedMemorySize, 65536);
        smem_set = 1;
    }

    router_fused<<<M / BM, NT, 65536>>>(hidden, Wg, Wn, noise, out, M);
}